// round 8
// baseline (speedup 1.0000x reference)
#include <cuda_runtime.h>
#include <cuda_bf16.h>
#include <math.h>

#define T_TOTAL 32768
#define NEXP    64
#define HDIM    1024
#define GRID    296            // 2 CTAs/SM, one wave
#define NTHR    256
#define KC      64
#define NCHUNK  (HDIM / KC)    // 16
#define EPS_TIE 5e-5f

#define A_LEV   16384          // one level: 128 rows x 128B
#define A_BYTES (3 * A_LEV)    // 48KB
#define B_CHUNK 24576          // 4 s x 3 lev x 4 npair x 32 lanes x 16B
#define B_BYTES (2 * B_CHUNK)  // 48KB double buffer
#define SMEM_REQ (A_BYTES + B_BYTES)   // 96KB

// W pre-split to bf16 h/m/l, stored in mma B-fragment register order
__device__ unsigned char g_Wfrag[NCHUNK * B_CHUNK];

__device__ __forceinline__ unsigned short splitb(float v, int lev) {
    __nv_bfloat16 h = __float2bfloat16(v);
    if (lev == 0) return __bfloat16_as_ushort(h);
    float r1 = v - __bfloat162float(h);
    __nv_bfloat16 m = __float2bfloat16(r1);
    if (lev == 1) return __bfloat16_as_ushort(m);
    return __bfloat16_as_ushort(__float2bfloat16(r1 - __bfloat162float(m)));
}

// one thread per 16B fragment word group: g = (((chunk*4+s)*3+lev)*4+npair)*32+lane
__global__ void prep_w_kernel(const float* __restrict__ W) {
    int g = blockIdx.x * blockDim.x + threadIdx.x;
    if (g >= NCHUNK * 1536) return;
    int lane = g & 31;
    int t = g >> 5;
    int npair = t & 3;  t >>= 2;
    int lev = t % 3;    t /= 3;
    int s = t & 3;
    int chunk = t >> 2;
    int k0 = chunk * KC + s * 16 + (lane & 3) * 2;
    unsigned w[4];
#pragma unroll
    for (int q = 0; q < 2; q++) {
        int e = (npair * 2 + q) * 8 + (lane >> 2);
        const float* We = W + (size_t)e * HDIM;
        w[q * 2 + 0] = (unsigned)splitb(We[k0], lev)
                     | ((unsigned)splitb(We[k0 + 1], lev) << 16);
        w[q * 2 + 1] = (unsigned)splitb(We[k0 + 8], lev)
                     | ((unsigned)splitb(We[k0 + 9], lev) << 16);
    }
    *(uint4*)&g_Wfrag[(size_t)g * 16] = make_uint4(w[0], w[1], w[2], w[3]);
}

#define CP_ASYNC16(dst_u32, src) \
    asm volatile("cp.async.cg.shared.global [%0], [%1], 16;" :: "r"(dst_u32), "l"(src))
#define CP_COMMIT()  asm volatile("cp.async.commit_group;")
#define CP_WAIT1()   asm volatile("cp.async.wait_group 1;")

#define LDMATRIX_X4(a, addr)                                            \
    asm volatile("ldmatrix.sync.aligned.m8n8.x4.shared.b16 {%0,%1,%2,%3}, [%4];" \
        : "=r"((a)[0]), "=r"((a)[1]), "=r"((a)[2]), "=r"((a)[3]) : "r"(addr))

#define MMA_BF16(d, a, b0, b1)                                          \
    asm volatile("mma.sync.aligned.m16n8k16.row.col.f32.bf16.bf16.f32 " \
        "{%0,%1,%2,%3}, {%4,%5,%6,%7}, {%8,%9}, {%0,%1,%2,%3};"         \
        : "+f"((d)[0]), "+f"((d)[1]), "+f"((d)[2]), "+f"((d)[3])        \
        : "r"((a)[0]), "r"((a)[1]), "r"((a)[2]), "r"((a)[3]), "r"(b0), "r"(b1))

__global__ __launch_bounds__(NTHR, 2)
void moe_gate_mma(const float* __restrict__ x,
                  const float* __restrict__ W,
                  float* __restrict__ out,
                  int out_size)
{
    extern __shared__ unsigned char dsm[];
    const unsigned smemA = (unsigned)__cvta_generic_to_shared(dsm);
    const unsigned smemB = smemA + A_BYTES;

    const int tid  = threadIdx.x;
    const int w    = tid >> 5;
    const int lane = tid & 31;
    const int wm   = w & 3;           // row group: rows 32*wm .. +31
    const int wn   = w >> 2;          // expert half: experts 32*wn .. +31
    const int m_base = wm * 32;
    const int n_base = wn * 32;
    const int np0  = wn * 2;

    const int start = (int)(((long long)blockIdx.x * T_TOTAL) / GRID);
    const int count = (int)(((long long)(blockIdx.x + 1) * T_TOTAL) / GRID) - start;
    const float* xblk = x + (size_t)start * HDIM;

    float acc[2][4][4];
#pragma unroll
    for (int mt = 0; mt < 2; mt++)
#pragma unroll
        for (int nt = 0; nt < 4; nt++)
#pragma unroll
            for (int i = 0; i < 4; i++) acc[mt][nt][i] = 0.0f;

    float4 xr[8];

    auto ldg_x = [&](int c) {
#pragma unroll
        for (int i = 0; i < 8; i++) {
            int idx = i * NTHR + tid;          // 2048 = 128 rows x 16 float4
            int row = idx >> 4, c4 = idx & 15;
            int gr = (row < count) ? row : 0;
            xr[i] = *(const float4*)&xblk[(size_t)gr * HDIM + c * KC + c4 * 4];
        }
    };

    auto sts_a = [&]() {
#pragma unroll
        for (int i = 0; i < 8; i++) {
            int idx = i * NTHR + tid;
            int row = idx >> 4, c4 = idx & 15;
            unsigned off = (unsigned)(row * 128)
                         + (((unsigned)((c4 >> 1) ^ (row & 7)) << 4) | ((c4 & 1) << 3));
            float v[4] = { xr[i].x, xr[i].y, xr[i].z, xr[i].w };
#pragma unroll
            for (int lev = 0; lev < 3; lev++) {
                unsigned w0 = (unsigned)splitb(v[0], lev) | ((unsigned)splitb(v[1], lev) << 16);
                unsigned w1 = (unsigned)splitb(v[2], lev) | ((unsigned)splitb(v[3], lev) << 16);
                *(uint2*)(dsm + lev * A_LEV + off) = make_uint2(w0, w1);
            }
        }
    };

    auto cp_b = [&](int c) {
        unsigned dbase = smemB + (c & 1) * B_CHUNK;
        const unsigned char* src = g_Wfrag + (size_t)c * B_CHUNK;
#pragma unroll
        for (int i = 0; i < 6; i++) {
            int idx = i * NTHR + tid;
            CP_ASYNC16(dbase + idx * 16, src + (size_t)idx * 16);
        }
    };

    ldg_x(0);
    cp_b(0); CP_COMMIT();

    for (int c = 0; c < NCHUNK; c++) {
        sts_a();
        if (c + 1 < NCHUNK) cp_b(c + 1);
        CP_COMMIT();
        CP_WAIT1();
        __syncthreads();

        if (c + 1 < NCHUNK) ldg_x(c + 1);

        const unsigned bbase = smemB + (c & 1) * B_CHUNK;
#pragma unroll
        for (int s = 0; s < 4; s++) {
            unsigned a[3][2][4];
#pragma unroll
            for (int lev = 0; lev < 3; lev++)
#pragma unroll
                for (int mt = 0; mt < 2; mt++) {
                    int arow = m_base + mt * 16 + ((lane >> 3) & 1) * 8 + (lane & 7);
                    unsigned addr = smemA + lev * A_LEV + arow * 128
                        + ((unsigned)(((s << 1) | ((lane >> 4) & 1)) ^ (arow & 7)) << 4);
                    LDMATRIX_X4(a[lev][mt], addr);
                }
#pragma unroll
            for (int blev = 0; blev < 3; blev++) {
                unsigned boff = bbase + (((s * 3 + blev) * 4 + np0) * 512) + lane * 16;
                uint4 b0, b1;
                asm volatile("ld.shared.v4.u32 {%0,%1,%2,%3}, [%4];"
                    : "=r"(b0.x), "=r"(b0.y), "=r"(b0.z), "=r"(b0.w) : "r"(boff));
                asm volatile("ld.shared.v4.u32 {%0,%1,%2,%3}, [%4];"
                    : "=r"(b1.x), "=r"(b1.y), "=r"(b1.z), "=r"(b1.w) : "r"(boff + 512));
#pragma unroll
                for (int alev = 0; alev < 3; alev++) {
                    if (alev < 3 - blev) {
#pragma unroll
                        for (int mt = 0; mt < 2; mt++) {
                            MMA_BF16(acc[mt][0], a[alev][mt], b0.x, b0.y);
                            MMA_BF16(acc[mt][1], a[alev][mt], b0.z, b0.w);
                            MMA_BF16(acc[mt][2], a[alev][mt], b1.x, b1.y);
                            MMA_BF16(acc[mt][3], a[alev][mt], b1.z, b1.w);
                        }
                    }
                }
            }
        }
        __syncthreads();
    }

    // ---------------- epilogue ----------------
    float* L = (float*)dsm;   // pitch 68 floats, conflict-free
    {
        int r0l = lane >> 2, c0l = (lane & 3) * 2;
#pragma unroll
        for (int mt = 0; mt < 2; mt++)
#pragma unroll
            for (int nt = 0; nt < 4; nt++) {
                int row = m_base + mt * 16 + r0l;
                int col = n_base + nt * 8 + c0l;
                *(float2*)&L[row * 68 + col]       = make_float2(acc[mt][nt][0], acc[mt][nt][1]);
                *(float2*)&L[(row + 8) * 68 + col] = make_float2(acc[mt][nt][2], acc[mt][nt][3]);
            }
    }
    __syncthreads();

    if (tid < 128) {
        int row = tid;
        if (row < count) {
            float l[64];
#pragma unroll
            for (int i = 0; i < 16; i++)
                *(float4*)&l[i * 4] = *(const float4*)&L[row * 68 + i * 4];

            float mx = l[0];
#pragma unroll
            for (int e = 1; e < NEXP; e++) mx = fmaxf(mx, l[e]);
            float sum = 0.0f;
#pragma unroll
            for (int e = 0; e < NEXP; e++) sum += expf(l[e] - mx);

            // top-3 (to measure the rank-2/rank-3 gap)
            float v1 = -INFINITY, v2 = -INFINITY, v3 = -INFINITY;
            int   i1 = 0, i2 = 0;
#pragma unroll
            for (int e = 0; e < NEXP; e++) {
                float lv = l[e];
                if (lv > v1)      { v3 = v2; v2 = v1; i2 = i1; v1 = lv; i1 = e; }
                else if (lv > v2) { v3 = v2; v2 = lv; i2 = e; }
                else if (lv > v3) { v3 = lv; }
            }

            // near-tie rescue: recompute logits in exact fp32 (rare path)
            if (v1 - v2 < EPS_TIE || v2 - v3 < EPS_TIE) {
                const float* xrow = xblk + (size_t)row * HDIM;
                v1 = -INFINITY; v2 = -INFINITY; i1 = 0; i2 = 0;
                for (int e = 0; e < NEXP; e++) {
                    const float* We = W + (size_t)e * HDIM;
                    float d0 = 0.f, d1 = 0.f, d2 = 0.f, d3 = 0.f;
                    for (int k = 0; k < HDIM; k += 4) {
                        float4 xa = *(const float4*)&xrow[k];
                        float4 wa = *(const float4*)&We[k];
                        d0 = fmaf(xa.x, wa.x, d0);
                        d1 = fmaf(xa.y, wa.y, d1);
                        d2 = fmaf(xa.z, wa.z, d2);
                        d3 = fmaf(xa.w, wa.w, d3);
                    }
                    float lv = (d0 + d1) + (d2 + d3);
                    if (lv > v1)      { v2 = v1; i2 = i1; v1 = lv; i1 = e; }
                    else if (lv > v2) { v2 = lv; i2 = e; }
                }
            }

            float p1 = expf(v1 - mx) / sum;
            float p2 = expf(v2 - mx) / sum;
            float e21 = expf(p2 - p1);
            float s1  = 1.0f / (1.0f + e21);
            float s2  = e21 * s1;

            int t = start + row;
            *(float2*)&out[2 * (size_t)t] = make_float2(s1, s2);
            *(float2*)&out[2 * (size_t)T_TOTAL + 2 * (size_t)t] =
                make_float2((float)i1, (float)i2);
        }
    }

    // tail (scalar zero output + anything past 4*T)
    if (blockIdx.x == 0 && tid < 32) {
        for (int p = 4 * T_TOTAL + tid; p < out_size; p += 32)
            out[p] = 0.0f;
    }
}

extern "C" void kernel_launch(void* const* d_in, const int* in_sizes, int n_in,
                              void* d_out, int out_size)
{
    const float* x = (const float*)d_in[0];
    const float* W = (const float*)d_in[1];
    float* out = (float*)d_out;

    static bool attr_set = false;
    if (!attr_set) {
        cudaFuncSetAttribute(moe_gate_mma,
                             cudaFuncAttributeMaxDynamicSharedMemorySize, SMEM_REQ);
        attr_set = true;
    }

    prep_w_kernel<<<(NCHUNK * 1536 + 255) / 256, 256>>>(W);
    moe_gate_mma<<<GRID, NTHR, SMEM_REQ>>>(x, W, out, out_size);
}

// round 9
// speedup vs baseline: 6.7314x; 6.7314x over previous
#include <cuda_runtime.h>
#include <cuda_bf16.h>
#include <math.h>

#define T_TOTAL 32768
#define NEXP    64
#define HDIM    1024
#define GRID    296            // 2 CTAs/SM, one wave
#define NTHR    256
#define KC      64
#define NCHUNK  (HDIM / KC)    // 16
#define EPS_TIE 1e-4f

#define A_LEV   16384          // one level: 128 rows x 128B
#define A_BYTES (3 * A_LEV)    // 48KB
#define B_CHUNK 24576          // 4 s x 3 lev x 4 npair x 32 lanes x 16B
#define B_BYTES (2 * B_CHUNK)  // 48KB double buffer
#define SMEM_REQ (A_BYTES + B_BYTES)   // 96KB

// W pre-split to bf16 h/m/l, stored in mma B-fragment register order
__device__ unsigned char g_Wfrag[NCHUNK * B_CHUNK];

__device__ __forceinline__ unsigned short splitb(float v, int lev) {
    __nv_bfloat16 h = __float2bfloat16(v);
    if (lev == 0) return __bfloat16_as_ushort(h);
    float r1 = v - __bfloat162float(h);
    __nv_bfloat16 m = __float2bfloat16(r1);
    if (lev == 1) return __bfloat16_as_ushort(m);
    return __bfloat16_as_ushort(__float2bfloat16(r1 - __bfloat162float(m)));
}

// one thread per 16B fragment word group: g = (((chunk*4+s)*3+lev)*4+npair)*32+lane
__global__ void prep_w_kernel(const float* __restrict__ W) {
    int g = blockIdx.x * blockDim.x + threadIdx.x;
    if (g >= NCHUNK * 1536) return;
    int lane = g & 31;
    int t = g >> 5;
    int npair = t & 3;  t >>= 2;
    int lev = t % 3;    t /= 3;
    int s = t & 3;
    int chunk = t >> 2;
    int k0 = chunk * KC + s * 16 + (lane & 3) * 2;
    unsigned w[4];
#pragma unroll
    for (int q = 0; q < 2; q++) {
        int e = (npair * 2 + q) * 8 + (lane >> 2);
        const float* We = W + (size_t)e * HDIM;
        w[q * 2 + 0] = (unsigned)splitb(We[k0], lev)
                     | ((unsigned)splitb(We[k0 + 1], lev) << 16);
        w[q * 2 + 1] = (unsigned)splitb(We[k0 + 8], lev)
                     | ((unsigned)splitb(We[k0 + 9], lev) << 16);
    }
    *(uint4*)&g_Wfrag[(size_t)g * 16] = make_uint4(w[0], w[1], w[2], w[3]);
}

#define CP_ASYNC16(dst_u32, src) \
    asm volatile("cp.async.cg.shared.global [%0], [%1], 16;" :: "r"(dst_u32), "l"(src))
#define CP_COMMIT()  asm volatile("cp.async.commit_group;")
#define CP_WAIT1()   asm volatile("cp.async.wait_group 1;")

#define LDMATRIX_X4(a, addr)                                            \
    asm volatile("ldmatrix.sync.aligned.m8n8.x4.shared.b16 {%0,%1,%2,%3}, [%4];" \
        : "=r"((a)[0]), "=r"((a)[1]), "=r"((a)[2]), "=r"((a)[3]) : "r"(addr))

#define MMA_BF16(d, a, b0, b1)                                          \
    asm volatile("mma.sync.aligned.m16n8k16.row.col.f32.bf16.bf16.f32 " \
        "{%0,%1,%2,%3}, {%4,%5,%6,%7}, {%8,%9}, {%0,%1,%2,%3};"         \
        : "+f"((d)[0]), "+f"((d)[1]), "+f"((d)[2]), "+f"((d)[3])        \
        : "r"((a)[0]), "r"((a)[1]), "r"((a)[2]), "r"((a)[3]), "r"(b0), "r"(b1))

__global__ __launch_bounds__(NTHR, 2)
void moe_gate_mma(const float* __restrict__ x,
                  const float* __restrict__ W,
                  float* __restrict__ out,
                  int out_size)
{
    extern __shared__ unsigned char dsm[];
    const unsigned smemA = (unsigned)__cvta_generic_to_shared(dsm);
    const unsigned smemB = smemA + A_BYTES;

    __shared__ int s_nflag;
    __shared__ int s_rows[128];

    const int tid  = threadIdx.x;
    const int w    = tid >> 5;
    const int lane = tid & 31;
    const int wm   = w & 3;           // row group: rows 32*wm .. +31
    const int wn   = w >> 2;          // expert half: experts 32*wn .. +31
    const int m_base = wm * 32;
    const int n_base = wn * 32;
    const int np0  = wn * 2;

    const int start = (int)(((long long)blockIdx.x * T_TOTAL) / GRID);
    const int count = (int)(((long long)(blockIdx.x + 1) * T_TOTAL) / GRID) - start;
    const float* xblk = x + (size_t)start * HDIM;

    if (tid == 0) s_nflag = 0;

    float acc[2][4][4];
#pragma unroll
    for (int mt = 0; mt < 2; mt++)
#pragma unroll
        for (int nt = 0; nt < 4; nt++)
#pragma unroll
            for (int i = 0; i < 4; i++) acc[mt][nt][i] = 0.0f;

    float4 xr[8];

    auto ldg_x = [&](int c) {
#pragma unroll
        for (int i = 0; i < 8; i++) {
            int idx = i * NTHR + tid;          // 2048 = 128 rows x 16 float4
            int row = idx >> 4, c4 = idx & 15;
            int gr = (row < count) ? row : 0;
            xr[i] = *(const float4*)&xblk[(size_t)gr * HDIM + c * KC + c4 * 4];
        }
    };

    auto sts_a = [&]() {
#pragma unroll
        for (int i = 0; i < 8; i++) {
            int idx = i * NTHR + tid;
            int row = idx >> 4, c4 = idx & 15;
            unsigned off = (unsigned)(row * 128)
                         + (((unsigned)((c4 >> 1) ^ (row & 7)) << 4) | ((c4 & 1) << 3));
            float v[4] = { xr[i].x, xr[i].y, xr[i].z, xr[i].w };
#pragma unroll
            for (int lev = 0; lev < 3; lev++) {
                unsigned w0 = (unsigned)splitb(v[0], lev) | ((unsigned)splitb(v[1], lev) << 16);
                unsigned w1 = (unsigned)splitb(v[2], lev) | ((unsigned)splitb(v[3], lev) << 16);
                *(uint2*)(dsm + lev * A_LEV + off) = make_uint2(w0, w1);
            }
        }
    };

    auto cp_b = [&](int c) {
        unsigned dbase = smemB + (c & 1) * B_CHUNK;
        const unsigned char* src = g_Wfrag + (size_t)c * B_CHUNK;
#pragma unroll
        for (int i = 0; i < 6; i++) {
            int idx = i * NTHR + tid;
            CP_ASYNC16(dbase + idx * 16, src + (size_t)idx * 16);
        }
    };

    ldg_x(0);
    cp_b(0); CP_COMMIT();

    for (int c = 0; c < NCHUNK; c++) {
        sts_a();
        if (c + 1 < NCHUNK) cp_b(c + 1);
        CP_COMMIT();
        CP_WAIT1();
        __syncthreads();

        if (c + 1 < NCHUNK) ldg_x(c + 1);

        const unsigned bbase = smemB + (c & 1) * B_CHUNK;
#pragma unroll
        for (int s = 0; s < 4; s++) {
            unsigned a[3][2][4];
#pragma unroll
            for (int lev = 0; lev < 3; lev++)
#pragma unroll
                for (int mt = 0; mt < 2; mt++) {
                    int arow = m_base + mt * 16 + ((lane >> 3) & 1) * 8 + (lane & 7);
                    unsigned addr = smemA + lev * A_LEV + arow * 128
                        + ((unsigned)(((s << 1) | ((lane >> 4) & 1)) ^ (arow & 7)) << 4);
                    LDMATRIX_X4(a[lev][mt], addr);
                }
#pragma unroll
            for (int blev = 0; blev < 3; blev++) {
                unsigned boff = bbase + (((s * 3 + blev) * 4 + np0) * 512) + lane * 16;
                uint4 b0, b1;
                asm volatile("ld.shared.v4.u32 {%0,%1,%2,%3}, [%4];"
                    : "=r"(b0.x), "=r"(b0.y), "=r"(b0.z), "=r"(b0.w) : "r"(boff));
                asm volatile("ld.shared.v4.u32 {%0,%1,%2,%3}, [%4];"
                    : "=r"(b1.x), "=r"(b1.y), "=r"(b1.z), "=r"(b1.w) : "r"(boff + 512));
#pragma unroll
                for (int alev = 0; alev < 3; alev++) {
                    if (alev < 3 - blev) {
#pragma unroll
                        for (int mt = 0; mt < 2; mt++) {
                            MMA_BF16(acc[mt][0], a[alev][mt], b0.x, b0.y);
                            MMA_BF16(acc[mt][1], a[alev][mt], b0.z, b0.w);
                            MMA_BF16(acc[mt][2], a[alev][mt], b1.x, b1.y);
                            MMA_BF16(acc[mt][3], a[alev][mt], b1.z, b1.w);
                        }
                    }
                }
            }
        }
        __syncthreads();
    }

    // ---------------- epilogue ----------------
    float* L = (float*)dsm;   // pitch 68 floats, conflict-free
    {
        int r0l = lane >> 2, c0l = (lane & 3) * 2;
#pragma unroll
        for (int mt = 0; mt < 2; mt++)
#pragma unroll
            for (int nt = 0; nt < 4; nt++) {
                int row = m_base + mt * 16 + r0l;
                int col = n_base + nt * 8 + c0l;
                *(float2*)&L[row * 68 + col]       = make_float2(acc[mt][nt][0], acc[mt][nt][1]);
                *(float2*)&L[(row + 8) * 68 + col] = make_float2(acc[mt][nt][2], acc[mt][nt][3]);
            }
    }
    __syncthreads();

    // --- phase 1: flag near-tie rows (top-3 gap test) ---
    if (tid < 128 && tid < count) {
        int row = tid;
        float v1 = -INFINITY, v2 = -INFINITY, v3 = -INFINITY;
#pragma unroll
        for (int e = 0; e < NEXP; e++) {
            float lv = L[row * 68 + e];
            if (lv > v1)      { v3 = v2; v2 = v1; v1 = lv; }
            else if (lv > v2) { v3 = v2; v2 = lv; }
            else if (lv > v3) { v3 = lv; }
        }
        if (v1 - v2 < EPS_TIE || v2 - v3 < EPS_TIE) {
            int slot = atomicAdd(&s_nflag, 1);
            s_rows[slot] = row;
        }
    }
    __syncthreads();

    // --- phase 2: cooperative exact-fp32 recompute of flagged rows ---
    {
        const int nf = s_nflag;
        const int e  = tid >> 2;        // expert 0..63
        const int q  = tid & 3;         // k-quarter
        for (int f = 0; f < nf; f++) {
            int row = s_rows[f];
            const float* xq = xblk + (size_t)row * HDIM + q * 256;
            const float* Wq = W + (size_t)e * HDIM + q * 256;
            float d0 = 0.f, d1 = 0.f, d2 = 0.f, d3 = 0.f;
#pragma unroll 8
            for (int kk = 0; kk < 64; kk++) {
                float4 xa = *(const float4*)&xq[kk * 4];
                float4 wa = *(const float4*)&Wq[kk * 4];
                d0 = fmaf(xa.x, wa.x, d0);
                d1 = fmaf(xa.y, wa.y, d1);
                d2 = fmaf(xa.z, wa.z, d2);
                d3 = fmaf(xa.w, wa.w, d3);
            }
            float v = (d0 + d1) + (d2 + d3);
            v += __shfl_xor_sync(0xffffffffu, v, 1);
            v += __shfl_xor_sync(0xffffffffu, v, 2);
            if (q == 0) L[row * 68 + e] = v;
        }
        if (nf) __syncthreads();
    }

    // --- phase 3: softmax + top-2 from (possibly corrected) logits ---
    if (tid < 128 && tid < count) {
        int row = tid;
        float l[64];
#pragma unroll
        for (int i = 0; i < 16; i++)
            *(float4*)&l[i * 4] = *(const float4*)&L[row * 68 + i * 4];

        float mx = l[0];
#pragma unroll
        for (int e = 1; e < NEXP; e++) mx = fmaxf(mx, l[e]);
        float sum = 0.0f;
#pragma unroll
        for (int e = 0; e < NEXP; e++) sum += expf(l[e] - mx);

        float v1 = -INFINITY, v2 = -INFINITY;
        int   i1 = 0, i2 = 0;
#pragma unroll
        for (int e = 0; e < NEXP; e++) {
            float lv = l[e];
            if (lv > v1)      { v2 = v1; i2 = i1; v1 = lv; i1 = e; }
            else if (lv > v2) { v2 = lv; i2 = e; }
        }

        float p1 = expf(v1 - mx) / sum;
        float p2 = expf(v2 - mx) / sum;
        float e21 = expf(p2 - p1);
        float s1  = 1.0f / (1.0f + e21);
        float s2  = e21 * s1;

        int t = start + row;
        *(float2*)&out[2 * (size_t)t] = make_float2(s1, s2);
        *(float2*)&out[2 * (size_t)T_TOTAL + 2 * (size_t)t] =
            make_float2((float)i1, (float)i2);
    }

    // tail (scalar zero output + anything past 4*T)
    if (blockIdx.x == 0 && tid < 32) {
        for (int p = 4 * T_TOTAL + tid; p < out_size; p += 32)
            out[p] = 0.0f;
    }
}

extern "C" void kernel_launch(void* const* d_in, const int* in_sizes, int n_in,
                              void* d_out, int out_size)
{
    const float* x = (const float*)d_in[0];
    const float* W = (const float*)d_in[1];
    float* out = (float*)d_out;

    static bool attr_set = false;
    if (!attr_set) {
        cudaFuncSetAttribute(moe_gate_mma,
                             cudaFuncAttributeMaxDynamicSharedMemorySize, SMEM_REQ);
        attr_set = true;
    }

    prep_w_kernel<<<(NCHUNK * 1536 + 255) / 256, 256>>>(W);
    moe_gate_mma<<<GRID, NTHR, SMEM_REQ>>>(x, W, out, out_size);
}

// round 10
// speedup vs baseline: 9.8833x; 1.4683x over previous
#include <cuda_runtime.h>
#include <cuda_bf16.h>
#include <math.h>

#define T_TOTAL 32768
#define NEXP    64
#define HDIM    1024
#define GRID    296            // 2 CTAs/SM, one wave
#define NTHR    256
#define KC      64
#define NCHUNK  (HDIM / KC)    // 16
#define EPS_TIE 2e-4f

#define A_LEV   16384          // one level: 128 rows x 128B
#define A_BUF   (2 * A_LEV)    // 2 levels per buffer
#define A_BYTES (2 * A_BUF)    // double buffered: 64KB
#define B_CHUNK 16384          // 4 s x 2 lev x 4 npair x 32 lanes x 16B
#define B_BYTES (2 * B_CHUNK)  // 32KB double buffer
#define SMEM_REQ (A_BYTES + B_BYTES)   // 96KB

// W pre-split to bf16 h/m, stored in mma B-fragment register order
__device__ unsigned char g_Wfrag[NCHUNK * B_CHUNK];

__device__ __forceinline__ unsigned short splitb2(float v, int lev) {
    __nv_bfloat16 h = __float2bfloat16(v);
    if (lev == 0) return __bfloat16_as_ushort(h);
    return __bfloat16_as_ushort(__float2bfloat16(v - __bfloat162float(h)));
}

// one thread per 16B fragment group: g = (((chunk*4+s)*2+lev)*4+npair)*32+lane
__global__ void prep_w_kernel(const float* __restrict__ W) {
    int g = blockIdx.x * blockDim.x + threadIdx.x;
    if (g >= NCHUNK * 1024) return;
    int lane = g & 31;
    int t = g >> 5;
    int npair = t & 3;  t >>= 2;
    int lev = t & 1;    t >>= 1;
    int s = t & 3;
    int chunk = t >> 2;
    int k0 = chunk * KC + s * 16 + (lane & 3) * 2;
    unsigned w[4];
#pragma unroll
    for (int q = 0; q < 2; q++) {
        int e = (npair * 2 + q) * 8 + (lane >> 2);
        const float* We = W + (size_t)e * HDIM;
        w[q * 2 + 0] = (unsigned)splitb2(We[k0], lev)
                     | ((unsigned)splitb2(We[k0 + 1], lev) << 16);
        w[q * 2 + 1] = (unsigned)splitb2(We[k0 + 8], lev)
                     | ((unsigned)splitb2(We[k0 + 9], lev) << 16);
    }
    *(uint4*)&g_Wfrag[(size_t)g * 16] = make_uint4(w[0], w[1], w[2], w[3]);
}

#define CP_ASYNC16(dst_u32, src) \
    asm volatile("cp.async.cg.shared.global [%0], [%1], 16;" :: "r"(dst_u32), "l"(src))
#define CP_COMMIT()  asm volatile("cp.async.commit_group;")
#define CP_WAIT1()   asm volatile("cp.async.wait_group 1;")
#define CP_WAIT0()   asm volatile("cp.async.wait_group 0;")

#define LDMATRIX_X4(a, addr)                                            \
    asm volatile("ldmatrix.sync.aligned.m8n8.x4.shared.b16 {%0,%1,%2,%3}, [%4];" \
        : "=r"((a)[0]), "=r"((a)[1]), "=r"((a)[2]), "=r"((a)[3]) : "r"(addr))

#define MMA_BF16(d, a, b0, b1)                                          \
    asm volatile("mma.sync.aligned.m16n8k16.row.col.f32.bf16.bf16.f32 " \
        "{%0,%1,%2,%3}, {%4,%5,%6,%7}, {%8,%9}, {%0,%1,%2,%3};"         \
        : "+f"((d)[0]), "+f"((d)[1]), "+f"((d)[2]), "+f"((d)[3])        \
        : "r"((a)[0]), "r"((a)[1]), "r"((a)[2]), "r"((a)[3]), "r"(b0), "r"(b1))

__global__ __launch_bounds__(NTHR, 2)
void moe_gate_mma(const float* __restrict__ x,
                  const float* __restrict__ W,
                  float* __restrict__ out,
                  int out_size)
{
    extern __shared__ unsigned char dsm[];
    const unsigned smemA = (unsigned)__cvta_generic_to_shared(dsm);
    const unsigned smemB = smemA + A_BYTES;

    __shared__ int s_nflag;
    __shared__ int s_rows[128];

    const int tid  = threadIdx.x;
    const int w    = tid >> 5;
    const int lane = tid & 31;
    const int wm   = w & 3;
    const int wn   = w >> 2;
    const int m_base = wm * 32;
    const int n_base = wn * 32;
    const int np0  = wn * 2;

    const int start = (int)(((long long)blockIdx.x * T_TOTAL) / GRID);
    const int count = (int)(((long long)(blockIdx.x + 1) * T_TOTAL) / GRID) - start;
    const float* xblk = x + (size_t)start * HDIM;

    if (tid == 0) s_nflag = 0;

    float acc[2][4][4];
#pragma unroll
    for (int mt = 0; mt < 2; mt++)
#pragma unroll
        for (int nt = 0; nt < 4; nt++)
#pragma unroll
            for (int i = 0; i < 4; i++) acc[mt][nt][i] = 0.0f;

    float4 xr[8];

    auto ldg_x = [&](int c) {
#pragma unroll
        for (int i = 0; i < 8; i++) {
            int idx = i * NTHR + tid;          // 2048 = 128 rows x 16 float4
            int row = idx >> 4, c4 = idx & 15;
            int gr = (row < count) ? row : 0;
            xr[i] = *(const float4*)&xblk[(size_t)gr * HDIM + c * KC + c4 * 4];
        }
    };

    auto sts_a = [&](int buf) {
        unsigned char* base = dsm + buf * A_BUF;
#pragma unroll
        for (int i = 0; i < 8; i++) {
            int idx = i * NTHR + tid;
            int row = idx >> 4, c4 = idx & 15;
            unsigned off = (unsigned)(row * 128)
                         + (((unsigned)((c4 >> 1) ^ (row & 7)) << 4) | ((c4 & 1) << 3));
            float v[4] = { xr[i].x, xr[i].y, xr[i].z, xr[i].w };
            unsigned short h[4], m[4];
#pragma unroll
            for (int j = 0; j < 4; j++) {
                __nv_bfloat16 hb = __float2bfloat16(v[j]);
                h[j] = __bfloat16_as_ushort(hb);
                m[j] = __bfloat16_as_ushort(__float2bfloat16(v[j] - __bfloat162float(hb)));
            }
            *(uint2*)(base + off) = make_uint2(
                (unsigned)h[0] | ((unsigned)h[1] << 16),
                (unsigned)h[2] | ((unsigned)h[3] << 16));
            *(uint2*)(base + A_LEV + off) = make_uint2(
                (unsigned)m[0] | ((unsigned)m[1] << 16),
                (unsigned)m[2] | ((unsigned)m[3] << 16));
        }
    };

    auto cp_b = [&](int c) {
        unsigned dbase = smemB + (c & 1) * B_CHUNK;
        const unsigned char* src = g_Wfrag + (size_t)c * B_CHUNK;
#pragma unroll
        for (int i = 0; i < 4; i++) {
            int idx = i * NTHR + tid;          // 1024 x 16B
            CP_ASYNC16(dbase + idx * 16, src + (size_t)idx * 16);
        }
    };

    // prologue
    ldg_x(0);
    cp_b(0); CP_COMMIT();
    sts_a(0);
    ldg_x(1);
    CP_WAIT0();            // B(0) resident
    __syncthreads();       // A(0) visible

    for (int c = 0; c < NCHUNK; c++) {
        if (c + 1 < NCHUNK) { cp_b(c + 1); CP_COMMIT(); }
        CP_WAIT1();        // B(c) resident (≤1 pending = B(c+1))

        const unsigned abase = smemA + (c & 1) * A_BUF;
        const unsigned bbase = smemB + (c & 1) * B_CHUNK;
#pragma unroll
        for (int s = 0; s < 4; s++) {
            unsigned a[2][2][4];
#pragma unroll
            for (int lev = 0; lev < 2; lev++)
#pragma unroll
                for (int mt = 0; mt < 2; mt++) {
                    int arow = m_base + mt * 16 + ((lane >> 3) & 1) * 8 + (lane & 7);
                    unsigned addr = abase + lev * A_LEV + arow * 128
                        + ((unsigned)(((s << 1) | ((lane >> 4) & 1)) ^ (arow & 7)) << 4);
                    LDMATRIX_X4(a[lev][mt], addr);
                }
#pragma unroll
            for (int blev = 0; blev < 2; blev++) {
                unsigned boff = bbase + (((s * 2 + blev) * 4 + np0) * 512) + lane * 16;
                uint4 b0, b1;
                asm volatile("ld.shared.v4.u32 {%0,%1,%2,%3}, [%4];"
                    : "=r"(b0.x), "=r"(b0.y), "=r"(b0.z), "=r"(b0.w) : "r"(boff));
                asm volatile("ld.shared.v4.u32 {%0,%1,%2,%3}, [%4];"
                    : "=r"(b1.x), "=r"(b1.y), "=r"(b1.z), "=r"(b1.w) : "r"(boff + 512));
                int amax = (blev == 0) ? 2 : 1;    // passes: hh, mH, hM
#pragma unroll
                for (int alev = 0; alev < 2; alev++) {
                    if (alev < amax) {
#pragma unroll
                        for (int mt = 0; mt < 2; mt++) {
                            MMA_BF16(acc[mt][0], a[alev][mt], b0.x, b0.y);
                            MMA_BF16(acc[mt][1], a[alev][mt], b0.z, b0.w);
                            MMA_BF16(acc[mt][2], a[alev][mt], b1.x, b1.y);
                            MMA_BF16(acc[mt][3], a[alev][mt], b1.z, b1.w);
                        }
                    }
                }
            }
        }

        // overlap: stage next A, prefetch x(c+2)
        if (c + 1 < NCHUNK) sts_a((c + 1) & 1);
        if (c + 2 < NCHUNK) ldg_x(c + 2);
        __syncthreads();   // A(c+1) visible; reads of A(c)/B(c) complete
    }

    // ---------------- epilogue ----------------
    float* L = (float*)dsm;   // pitch 68 floats, conflict-free
    {
        int r0l = lane >> 2, c0l = (lane & 3) * 2;
#pragma unroll
        for (int mt = 0; mt < 2; mt++)
#pragma unroll
            for (int nt = 0; nt < 4; nt++) {
                int row = m_base + mt * 16 + r0l;
                int col = n_base + nt * 8 + c0l;
                *(float2*)&L[row * 68 + col]       = make_float2(acc[mt][nt][0], acc[mt][nt][1]);
                *(float2*)&L[(row + 8) * 68 + col] = make_float2(acc[mt][nt][2], acc[mt][nt][3]);
            }
    }
    __syncthreads();

    // --- phase 1: flag near-tie rows (top-3 gap test) ---
    if (tid < 128 && tid < count) {
        int row = tid;
        float v1 = -INFINITY, v2 = -INFINITY, v3 = -INFINITY;
#pragma unroll
        for (int e = 0; e < NEXP; e++) {
            float lv = L[row * 68 + e];
            if (lv > v1)      { v3 = v2; v2 = v1; v1 = lv; }
            else if (lv > v2) { v3 = v2; v2 = lv; }
            else if (lv > v3) { v3 = lv; }
        }
        if (v1 - v2 < EPS_TIE || v2 - v3 < EPS_TIE) {
            int slot = atomicAdd(&s_nflag, 1);
            s_rows[slot] = row;
        }
    }
    __syncthreads();

    // --- phase 2: cooperative exact-fp32 recompute of flagged rows ---
    {
        const int nf = s_nflag;
        const int e  = tid >> 2;
        const int q  = tid & 3;
        for (int f = 0; f < nf; f++) {
            int row = s_rows[f];
            const float* xq = xblk + (size_t)row * HDIM + q * 256;
            const float* Wq = W + (size_t)e * HDIM + q * 256;
            float d0 = 0.f, d1 = 0.f, d2 = 0.f, d3 = 0.f;
#pragma unroll 8
            for (int kk = 0; kk < 64; kk++) {
                float4 xa = *(const float4*)&xq[kk * 4];
                float4 wa = *(const float4*)&Wq[kk * 4];
                d0 = fmaf(xa.x, wa.x, d0);
                d1 = fmaf(xa.y, wa.y, d1);
                d2 = fmaf(xa.z, wa.z, d2);
                d3 = fmaf(xa.w, wa.w, d3);
            }
            float v = (d0 + d1) + (d2 + d3);
            v += __shfl_xor_sync(0xffffffffu, v, 1);
            v += __shfl_xor_sync(0xffffffffu, v, 2);
            if (q == 0) L[row * 68 + e] = v;
        }
        if (nf) __syncthreads();
    }

    // --- phase 3: softmax + top-2 from (possibly corrected) logits ---
    if (tid < 128 && tid < count) {
        int row = tid;
        float l[64];
#pragma unroll
        for (int i = 0; i < 16; i++)
            *(float4*)&l[i * 4] = *(const float4*)&L[row * 68 + i * 4];

        float mx = l[0];
#pragma unroll
        for (int e = 1; e < NEXP; e++) mx = fmaxf(mx, l[e]);
        float sum = 0.0f;
#pragma unroll
        for (int e = 0; e < NEXP; e++) sum += expf(l[e] - mx);

        float v1 = -INFINITY, v2 = -INFINITY;
        int   i1 = 0, i2 = 0;
#pragma unroll
        for (int e = 0; e < NEXP; e++) {
            float lv = l[e];
            if (lv > v1)      { v2 = v1; i2 = i1; v1 = lv; i1 = e; }
            else if (lv > v2) { v2 = lv; i2 = e; }
        }

        float p1 = expf(v1 - mx) / sum;
        float p2 = expf(v2 - mx) / sum;
        float e21 = expf(p2 - p1);
        float s1  = 1.0f / (1.0f + e21);
        float s2  = e21 * s1;

        int t = start + row;
        *(float2*)&out[2 * (size_t)t] = make_float2(s1, s2);
        *(float2*)&out[2 * (size_t)T_TOTAL + 2 * (size_t)t] =
            make_float2((float)i1, (float)i2);
    }

    // tail (scalar zero output + anything past 4*T)
    if (blockIdx.x == 0 && tid < 32) {
        for (int p = 4 * T_TOTAL + tid; p < out_size; p += 32)
            out[p] = 0.0f;
    }
}

extern "C" void kernel_launch(void* const* d_in, const int* in_sizes, int n_in,
                              void* d_out, int out_size)
{
    const float* x = (const float*)d_in[0];
    const float* W = (const float*)d_in[1];
    float* out = (float*)d_out;

    static bool attr_set = false;
    if (!attr_set) {
        cudaFuncSetAttribute(moe_gate_mma,
                             cudaFuncAttributeMaxDynamicSharedMemorySize, SMEM_REQ);
        attr_set = true;
    }

    prep_w_kernel<<<(NCHUNK * 1024 + 255) / 256, 256>>>(W);
    moe_gate_mma<<<GRID, NTHR, SMEM_REQ>>>(x, W, out, out_size);
}